// round 2
// baseline (speedup 1.0000x reference)
#include <cuda_runtime.h>
#include <cstdint>
#include <cstddef>

#define NA 2048
#define HH 128
#define NE 32768
#define RR 32
#define NH (NA*HH)
#define CUT 4.5f

// ---------------- scratch (static device globals; no allocations) ----------------
__device__ float g_ea[NE*384];      // edge MLP output, [E][384] (h-major, 3 comps inner)
__device__ float g_Xn[NH*9];        // normalized X
__device__ float g_cA[9*NH];        // compact planes of Xn (pre-mix)
__device__ float g_cM[9*NH];        // compact planes after chan_mix (I,A,S mixed)
__device__ float g_c2[9*NH];        // compact planes of scaled/normalized AB
__device__ float g_dXc[9*NH];       // compact planes of dX (after 2nd chan_mix)
__device__ float g_W1T[2*RR*HH];        // [l][k][j]  k-major transposes
__device__ float g_W2T[2*HH*256];
__device__ float g_W3T[2*256*384];
__device__ float g_WtT[12*HH*HH];       // [l*6+m][h][g]
__device__ int   g_cnt[NA];
__device__ int   g_cur[NA];
__device__ int   g_row[NA+1];
__device__ int   g_eord[NE];

typedef unsigned long long u64;

// ---------------- helpers ----------------
__device__ __forceinline__ u64 pk(float a, float b){
    u64 r; asm("mov.b64 %0, {%1,%2};" : "=l"(r) : "f"(a), "f"(b)); return r;
}
__device__ __forceinline__ void upk(u64 v, float& a, float& b){
    asm("mov.b64 {%0,%1}, %2;" : "=f"(a), "=f"(b) : "l"(v));
}
__device__ __forceinline__ void fma2(u64& d, u64 a, u64 b){
    asm("fma.rn.f32x2 %0, %1, %2, %0;" : "+l"(d) : "l"(a), "l"(b));
}
__device__ __forceinline__ float siluf(float x){ return x / (1.f + __expf(-x)); }

// compact order: {i0, a01, a02, a12, s00, s01, s02, s11, s12}
__device__ __forceinline__ void tocompact(const float* t, float s, float* c){
    float i0 = (t[0]+t[4]+t[8])*(1.f/3.f);
    c[0] = i0*s;
    c[1] = 0.5f*(t[1]-t[3])*s;
    c[2] = 0.5f*(t[2]-t[6])*s;
    c[3] = 0.5f*(t[5]-t[7])*s;
    c[4] = (t[0]-i0)*s;
    c[5] = 0.5f*(t[1]+t[3])*s;
    c[6] = 0.5f*(t[2]+t[6])*s;
    c[7] = (t[4]-i0)*s;
    c[8] = 0.5f*(t[5]+t[7])*s;
}
__device__ __forceinline__ void rec(const float* c, float* t){
    float i0=c[0], a01=c[1], a02=c[2], a12=c[3];
    float s00=c[4], s01=c[5], s02=c[6], s11=c[7], s12=c[8];
    t[0]=i0+s00;  t[1]=a01+s01; t[2]=a02+s02;
    t[3]=s01-a01; t[4]=i0+s11;  t[5]=a12+s12;
    t[6]=s02-a02; t[7]=s12-a12; t[8]=i0-s00-s11;
}
__device__ __forceinline__ void mmadd(const float* A, const float* B, float* C){
    #pragma unroll
    for(int i=0;i<3;i++){
        #pragma unroll
        for(int j=0;j<3;j++)
            C[i*3+j] += A[i*3+0]*B[0*3+j] + A[i*3+1]*B[1*3+j] + A[i*3+2]*B[2*3+j];
    }
}

// ---------------- weight transposes (once per launch) ----------------
__global__ void k_transpose(const float* __restrict__ Ws1, const float* __restrict__ Ws2,
                            const float* __restrict__ Ws3, const float* __restrict__ Wt){
    int stride = gridDim.x*blockDim.x;
    int t0 = blockIdx.x*blockDim.x + threadIdx.x;
    for(int i=t0;i<2*128*32;i+=stride){
        int l=i/4096, r=i%4096, j=r/32, k=r%32;
        g_W1T[l*4096 + k*128 + j] = Ws1[i];
    }
    for(int i=t0;i<2*256*128;i+=stride){
        int l=i/32768, r=i%32768, j=r/128, k=r%128;
        g_W2T[l*32768 + k*256 + j] = Ws2[i];
    }
    for(int i=t0;i<2*384*256;i+=stride){
        int l=i/98304, r=i%98304, j=r/256, k=r%256;
        g_W3T[l*98304 + k*384 + j] = Ws3[i];
    }
    for(int i=t0;i<12*128*128;i+=stride){
        int lm=i/16384, r=i%16384, g=r/128, hh=r%128;
        g_WtT[lm*16384 + hh*128 + g] = Wt[i];
    }
}

// ---------------- CSR build (edge_index is layer-invariant) ----------------
__global__ void k_zero_cnt(){
    int i = blockIdx.x*blockDim.x + threadIdx.x;
    if(i<NA){ g_cnt[i]=0; g_cur[i]=0; }
}
__global__ void k_count(const int* __restrict__ ei){
    int e = blockIdx.x*blockDim.x + threadIdx.x;
    if(e<NE) atomicAdd(&g_cnt[ei[e]], 1);
}
__global__ void k_scan(){
    __shared__ int sh[NA];
    int t = threadIdx.x;
    for(int i=t;i<NA;i+=1024) sh[i]=g_cnt[i];
    __syncthreads();
    int n = blockIdx.x*1024 + t;
    int acc=0;
    for(int m=0;m<NA;m++){ int v=sh[m]; acc += (m<n)? v : 0; }
    g_row[n]=acc;
    if(n==NA-1) g_row[NA]=acc+sh[NA-1];
}
__global__ void k_place(const int* __restrict__ ei){
    int e = blockIdx.x*blockDim.x + threadIdx.x;
    if(e<NE){
        int s = ei[e];
        int p = atomicAdd(&g_cur[s],1);
        g_eord[g_row[s]+p] = e;
    }
}

// ---------------- node prep: normalize + compact decompose ----------------
__global__ void k_node_prep(const float* __restrict__ Xin){
    int idx = blockIdx.x*blockDim.x + threadIdx.x;
    if(idx>=NH) return;
    float t[9]; float nrm=0.f;
    #pragma unroll
    for(int r=0;r<9;r++){ t[r]=Xin[(size_t)idx*9+r]; nrm += t[r]*t[r]; }
    float inv = 1.f/(nrm+1.f);
    #pragma unroll
    for(int r=0;r<9;r++){ t[r]*=inv; g_Xn[(size_t)idx*9+r]=t[r]; }
    float c[9]; tocompact(t,1.f,c);
    #pragma unroll
    for(int d=0;d<9;d++) g_cA[d*NH+idx]=c[d];
}

// ---------------- channel mix: 9 x [2048,128]x[128,128] batched GEMM ----------------
__global__ void __launch_bounds__(128) k_mix(int which, int wbase){
    __shared__ float sin_[32*128];
    const float* in  = which ? g_c2  : g_cA;
    float*       out = which ? g_dXc : g_cM;
    int d = blockIdx.y;
    int m = (d==0)?0:((d<4)?1:2);
    const float* W = g_WtT + (size_t)(wbase+m)*16384;   // [h][g]
    int n0 = blockIdx.x*32;
    const float* src = in + (size_t)d*NH + (size_t)n0*HH;
    for(int i=threadIdx.x;i<1024;i+=128)
        ((float4*)sin_)[i] = ((const float4*)src)[i];
    __syncthreads();
    int w = threadIdx.x>>5, lane = threadIdx.x&31;
    u64 acc[8][2];
    #pragma unroll
    for(int i=0;i<8;i++){ acc[i][0]=0ull; acc[i][1]=0ull; }
    for(int k=0;k<128;k++){
        float4 wf = *(const float4*)&W[k*128 + lane*4];
        u64 w0=pk(wf.x,wf.y), w1=pk(wf.z,wf.w);
        #pragma unroll
        for(int i=0;i<8;i++){
            float v = sin_[(w*8+i)*128 + k];
            u64 vp = pk(v,v);
            fma2(acc[i][0],vp,w0); fma2(acc[i][1],vp,w1);
        }
    }
    float* dst = out + (size_t)d*NH + (size_t)n0*HH;
    #pragma unroll
    for(int i=0;i<8;i++){
        float4 o; upk(acc[i][0],o.x,o.y); upk(acc[i][1],o.z,o.w);
        *(float4*)&dst[(w*8+i)*HH + lane*4] = o;
    }
}

// ---------------- edge MLP (32 edges/block, f32x2 register tiling) ----------------
__global__ void __launch_bounds__(128,4) k_mlp(const float* __restrict__ attr,
                                               const float* __restrict__ ewt,
                                               const float* __restrict__ b1,
                                               const float* __restrict__ b2,
                                               const float* __restrict__ b3,
                                               int l){
    __shared__ float s[12288];                 // 48KB exactly
    float* s_h1   = s;                          // 32*128
    float* s_h2   = s + 4096;                   // 32*256
    float* s_attr = s + 4096;                   // alias: 32*32, stage-1 only
    const float* W1 = g_W1T + l*4096;
    const float* W2 = g_W2T + l*32768;
    const float* W3 = g_W3T + l*98304;
    int e0 = blockIdx.x*32;
    int warp = threadIdx.x>>5, lane = threadIdx.x&31;
    int ew_ = warp*8;

    #pragma unroll
    for(int r=0;r<8;r++)
        s_attr[(ew_+r)*32 + lane] = attr[(size_t)(e0+ew_+r)*32 + lane];
    float cval = 0.f;
    if(lane<8){
        float wv = ewt[e0+ew_+lane];
        cval = (wv < CUT) ? 0.5f*(cosf(wv*(3.14159265358979f/CUT))+1.f) : 0.f;
    }
    __syncwarp();

    // stage 1: [32] -> [128]
    u64 a1[8][2];
    {
        float4 bb = *(const float4*)&b1[lane*4];
        u64 p0=pk(bb.x,bb.y), p1=pk(bb.z,bb.w);
        #pragma unroll
        for(int i=0;i<8;i++){ a1[i][0]=p0; a1[i][1]=p1; }
        for(int k=0;k<32;k++){
            float4 wf = *(const float4*)&W1[k*128 + lane*4];
            u64 w0=pk(wf.x,wf.y), w1p=pk(wf.z,wf.w);
            #pragma unroll
            for(int i=0;i<8;i++){
                float v = s_attr[(ew_+i)*32 + k];
                u64 vp = pk(v,v);
                fma2(a1[i][0],vp,w0); fma2(a1[i][1],vp,w1p);
            }
        }
    }
    #pragma unroll
    for(int i=0;i<8;i++){
        float x0,x1,x2,x3; upk(a1[i][0],x0,x1); upk(a1[i][1],x2,x3);
        *(float4*)&s_h1[(ew_+i)*128 + lane*4] =
            make_float4(siluf(x0),siluf(x1),siluf(x2),siluf(x3));
    }
    __syncthreads();   // all warps done with s_attr before s_h2 (alias) is written

    // stage 2: [128] -> [256]
    u64 a2[8][4];
    {
        float4 ba = *(const float4*)&b2[lane*4];
        float4 bq = *(const float4*)&b2[128 + lane*4];
        u64 p0=pk(ba.x,ba.y), p1=pk(ba.z,ba.w), p2=pk(bq.x,bq.y), p3=pk(bq.z,bq.w);
        #pragma unroll
        for(int i=0;i<8;i++){ a2[i][0]=p0; a2[i][1]=p1; a2[i][2]=p2; a2[i][3]=p3; }
        for(int k=0;k<128;k++){
            float4 wa = *(const float4*)&W2[k*256 + lane*4];
            float4 wb = *(const float4*)&W2[k*256 + 128 + lane*4];
            u64 q0=pk(wa.x,wa.y), q1=pk(wa.z,wa.w), q2=pk(wb.x,wb.y), q3=pk(wb.z,wb.w);
            #pragma unroll
            for(int i=0;i<8;i++){
                float v = s_h1[(ew_+i)*128 + k];
                u64 vp = pk(v,v);
                fma2(a2[i][0],vp,q0); fma2(a2[i][1],vp,q1);
                fma2(a2[i][2],vp,q2); fma2(a2[i][3],vp,q3);
            }
        }
    }
    #pragma unroll
    for(int i=0;i<8;i++){
        float x0,x1,x2,x3,x4,x5,x6,x7;
        upk(a2[i][0],x0,x1); upk(a2[i][1],x2,x3);
        upk(a2[i][2],x4,x5); upk(a2[i][3],x6,x7);
        *(float4*)&s_h2[(ew_+i)*256 + lane*4] =
            make_float4(siluf(x0),siluf(x1),siluf(x2),siluf(x3));
        *(float4*)&s_h2[(ew_+i)*256 + 128 + lane*4] =
            make_float4(siluf(x4),siluf(x5),siluf(x6),siluf(x7));
    }
    __syncwarp();

    // stage 3: [256] -> [384], two passes of 4 edges
    #pragma unroll 1
    for(int p=0;p<2;p++){
        u64 a3[4][6];
        #pragma unroll
        for(int mm=0;mm<3;mm++){
            float4 bb = *(const float4*)&b3[mm*128 + lane*4];
            u64 p0=pk(bb.x,bb.y), p1=pk(bb.z,bb.w);
            #pragma unroll
            for(int i=0;i<4;i++){ a3[i][mm*2]=p0; a3[i][mm*2+1]=p1; }
        }
        for(int k=0;k<256;k++){
            float4 w0f = *(const float4*)&W3[k*384 + lane*4];
            float4 w1f = *(const float4*)&W3[k*384 + 128 + lane*4];
            float4 w2f = *(const float4*)&W3[k*384 + 256 + lane*4];
            u64 q0=pk(w0f.x,w0f.y), q1=pk(w0f.z,w0f.w);
            u64 q2=pk(w1f.x,w1f.y), q3=pk(w1f.z,w1f.w);
            u64 q4=pk(w2f.x,w2f.y), q5=pk(w2f.z,w2f.w);
            #pragma unroll
            for(int i=0;i<4;i++){
                float v = s_h2[(ew_+p*4+i)*256 + k];
                u64 vp = pk(v,v);
                fma2(a3[i][0],vp,q0); fma2(a3[i][1],vp,q1);
                fma2(a3[i][2],vp,q2); fma2(a3[i][3],vp,q3);
                fma2(a3[i][4],vp,q4); fma2(a3[i][5],vp,q5);
            }
        }
        #pragma unroll
        for(int i=0;i<4;i++){
            float ce = __shfl_sync(0xffffffffu, cval, p*4+i);
            float* dst = g_ea + (size_t)(e0+ew_+p*4+i)*384;
            #pragma unroll
            for(int mm=0;mm<3;mm++){
                float x0,x1,x2,x3;
                upk(a3[i][mm*2],x0,x1); upk(a3[i][mm*2+1],x2,x3);
                *(float4*)&dst[mm*128 + lane*4] =
                    make_float4(siluf(x0)*ce, siluf(x1)*ce, siluf(x2)*ce, siluf(x3)*ce);
            }
        }
    }
}

// ---------------- gather segment-sum + full O(3) node update (fused) ----------------
__global__ void __launch_bounds__(128) k_gather_update(const int* __restrict__ ei,
                                                       const float* __restrict__ q){
    int n = blockIdx.x;
    int h = threadIdx.x;
    int s = g_row[n], e1 = g_row[n+1];
    float cm[9];
    #pragma unroll
    for(int d=0;d<9;d++) cm[d]=0.f;
    for(int t=s;t<e1;t++){
        int e = g_eord[t];
        int dst = ei[NE + e];
        const float* ep = g_ea + (size_t)e*384 + h*3;
        float a0=ep[0], a1=ep[1], a2=ep[2];
        int di = dst*HH + h;
        cm[0] += a0*g_cM[0*NH+di];
        cm[1] += a1*g_cM[1*NH+di];
        cm[2] += a1*g_cM[2*NH+di];
        cm[3] += a1*g_cM[3*NH+di];
        cm[4] += a2*g_cM[4*NH+di];
        cm[5] += a2*g_cM[5*NH+di];
        cm[6] += a2*g_cM[6*NH+di];
        cm[7] += a2*g_cM[7*NH+di];
        cm[8] += a2*g_cM[8*NH+di];
    }
    int idx = n*HH + h;
    float cy[9];
    #pragma unroll
    for(int d=0;d<9;d++) cy[d]=g_cM[d*NH+idx];
    float M[9], Y[9];
    rec(cm,M); rec(cy,Y);
    float AB[9];
    #pragma unroll
    for(int r=0;r<9;r++) AB[r]=0.f;
    mmadd(M,Y,AB); mmadd(Y,M,AB);
    float f = 1.f + 0.1f*q[n];
    float T[9]; float nrm=0.f;
    #pragma unroll
    for(int r=0;r<9;r++){ T[r]=f*AB[r]; nrm += T[r]*T[r]; }
    float inv = 1.f/(nrm+1.f);
    float c2[9]; tocompact(T,inv,c2);
    #pragma unroll
    for(int d=0;d<9;d++) g_c2[d*NH+idx]=c2[d];
}

// ---------------- final node update ----------------
__global__ void k_upd_b(const float* __restrict__ q, float* __restrict__ Xout){
    int idx = blockIdx.x*blockDim.x + threadIdx.x;
    if(idx>=NH) return;
    float c[9];
    #pragma unroll
    for(int d=0;d<9;d++) c[d]=g_dXc[d*NH+idx];
    float dx[9]; rec(c,dx);
    float f = 1.f + 0.1f*q[idx>>7];
    float D2[9];
    #pragma unroll
    for(int r=0;r<9;r++) D2[r]=0.f;
    mmadd(dx,dx,D2);
    #pragma unroll
    for(int r=0;r<9;r++)
        Xout[(size_t)idx*9+r] = g_Xn[(size_t)idx*9+r] + dx[r] + f*D2[r];
}

// ---------------- launcher ----------------
extern "C" void kernel_launch(void* const* d_in, const int* in_sizes, int n_in,
                              void* d_out, int out_size){
    const float* X    = (const float*)d_in[0];
    const float* attr = (const float*)d_in[1];
    const float* ewt  = (const float*)d_in[2];
    const float* q    = (const float*)d_in[3];
    const float* bs1  = (const float*)d_in[5];
    const float* bs2  = (const float*)d_in[7];
    const float* bs3  = (const float*)d_in[9];
    const float* Ws1  = (const float*)d_in[4];
    const float* Ws2  = (const float*)d_in[6];
    const float* Ws3  = (const float*)d_in[8];
    const float* Wt   = (const float*)d_in[10];
    const int*   ei   = (const int*)d_in[11];
    float* out = (float*)d_out;

    k_transpose<<<264,256>>>(Ws1,Ws2,Ws3,Wt);
    k_zero_cnt<<<(NA+255)/256,256>>>();
    k_count<<<NE/256,256>>>(ei);
    k_scan<<<2,1024>>>();
    k_place<<<NE/256,256>>>(ei);

    for(int l=0;l<2;l++){
        k_node_prep<<<NH/256,256>>>(l==0 ? X : out);
        k_mix<<<dim3(64,9),128>>>(0, l*6);
        k_mlp<<<NE/32,128>>>(attr, ewt, bs1+l*128, bs2+l*256, bs3+l*384, l);
        k_gather_update<<<NA,128>>>(ei, q);
        k_mix<<<dim3(64,9),128>>>(1, l*6+3);
        k_upd_b<<<NH/256,256>>>(q, out);
    }
}